// round 5
// baseline (speedup 1.0000x reference)
#include <cuda_runtime.h>
#include <cuda_bf16.h>

#define BATCH 256
#define PPAIR 1024
#define TPTS  100
#define NGRID 65536
#define KMAX  2
#define NBUCK 32

__global__ __launch_bounds__(1024, 2)
void pl_kernel(const float* __restrict__ inputs,
               const int*   __restrict__ dim_idx,
               const int*   __restrict__ birth_loc,
               const int*   __restrict__ death_loc,
               float* __restrict__ land,    // [B, 2, T, 2]
               float* __restrict__ trange)  // [B, 4]
{
    __shared__ float  s_b[PPAIR], s_d[PPAIR];
    __shared__ int    s_dim[PPAIR];
    __shared__ __align__(16) float2 pairs[2][PPAIR];  // bucket-ordered (mid, half)
    __shared__ float2 s_part[2][4][128];              // [dim][chunk][t] partial top-2
    __shared__ int    s_hist[2][NBUCK];
    __shared__ int    s_off [2][NBUCK + 1];           // descending-bucket offsets
    __shared__ int    s_pos [2][NBUCK];               // scatter cursors
    __shared__ int    s_cnt[2];                       // ORIGINAL per-dim pair counts
    __shared__ float  s_tmin[2], s_tmax[2];
    __shared__ unsigned s_hmax[2], s_max[2];

    const int b    = blockIdx.x;
    const int tid  = threadIdx.x;
    const int lane = tid & 31;
    const int w    = tid >> 5;

    if (tid < 2 * NBUCK) s_hist[tid >> 5][tid & 31] = 0;
    if (tid < 2) { s_cnt[tid] = 0; s_hmax[tid] = 0u; s_max[tid] = 0u; }
    __syncthreads();

    const float* __restrict__ row = inputs + (size_t)b * NGRID;

    // ---- Gather (1 pair/thread) + original-order arrays + per-dim count & hmax
    const int   d  = dim_idx  [b * PPAIR + tid];
    const float vb = __ldg(row + birth_loc[b * PPAIR + tid]);
    const float vd = __ldg(row + death_loc[b * PPAIR + tid]);
    s_dim[tid] = d; s_b[tid] = vb; s_d[tid] = vd;
    const float half = 0.5f * (vd - vb);              // >= 0 by construction
    {
        unsigned mk1 = __ballot_sync(0xffffffffu, d == 1);
        unsigned hb  = __float_as_uint(half);
        unsigned h0  = __reduce_max_sync(0xffffffffu, d == 0 ? hb : 0u);
        unsigned h1  = __reduce_max_sync(0xffffffffu, d == 1 ? hb : 0u);
        if (lane == 0) {
            atomicAdd(&s_cnt[1], __popc(mk1));
            atomicAdd(&s_cnt[0], 32 - __popc(mk1));
            atomicMax(&s_hmax[0], h0);
            atomicMax(&s_hmax[1], h1);
        }
    }
    __syncthreads();

    // ---- t-range from the FIRST KMAX valid pairs in original order (~4 iters)
    if (tid < 2) {
        const int dim = tid;
        float tmin = 1e30f, tmax = -1e30f;
        int found = 0;
        for (int p = 0; p < PPAIR && found < KMAX; p++) {
            if (s_dim[p] == dim) {
                tmin = fminf(tmin, s_b[p]);
                tmax = fmaxf(tmax, s_d[p]);
                found++;
            }
        }
        if (s_cnt[dim] == 0) { tmin = 0.0f; tmax = 0.0f; }
        s_tmin[dim] = tmin; s_tmax[dim] = tmax;
    }
    __syncthreads();

    // ---- Filter + histogram (keep only pairs that can be positive in [tmin,tmax])
    const bool keep = (vd > s_tmin[d]) && (vb < s_tmax[d]);
    int bk = 0;
    {
        float hmax = __uint_as_float(s_hmax[d]);
        float inv  = hmax > 0.0f ? (float)NBUCK / hmax : 0.0f;
        bk = min(NBUCK - 1, (int)(half * inv));
        if (keep) atomicAdd(&s_hist[d][bk], 1);
    }
    __syncthreads();

    // ---- Descending-bucket prefix (64 threads, 32 adds each)
    if (tid < 2 * NBUCK) {
        int dd = tid >> 5, kk = tid & 31;
        int st = 0;
        for (int q = kk + 1; q < NBUCK; q++) st += s_hist[dd][q];
        s_pos[dd][kk] = st;
        s_off[dd][NBUCK - 1 - kk] = st;
        if (kk == 0) s_off[dd][NBUCK] = st + s_hist[dd][0];
    }
    __syncthreads();

    // ---- Scatter into bucket-ordered array
    if (keep) {
        int pos = atomicAdd(&s_pos[d][bk], 1);
        pairs[d][pos] = make_float2(0.5f * (vb + vd), half);  // (mid, half)
    }
    __syncthreads();

    // ---- Phase 2: 32 warps = 2 dims * 4 t-groups(128 t) * 4 chunks.
    // Buckets high->low; warp exits when no remaining half-width can beat m2.
    {
        const int dim   = w >> 4;             // warp-uniform
        const int tgrp  = (w >> 2) & 3;
        const int chunk = w & 3;
        const int t     = tgrp * 32 + lane;   // 0..127

        const float tmn = s_tmin[dim], tmx = s_tmax[dim];
        const float tv  = tmn + (tmx - tmn) * ((float)t * (1.0f / (float)(TPTS - 1)));
        const float ubs = __uint_as_float(s_hmax[dim]) * (1.0002f / (float)NBUCK);
        const float2* __restrict__ pr = pairs[dim];
        const int* __restrict__ off = s_off[dim];

        float m1 = 0.0f, m2 = 0.0f;
        for (int j = 0; j < NBUCK; j++) {
            float upper = (float)(NBUCK - j) * ubs;   // >= any half in buckets j..31
            bool done = (t >= TPTS) || (upper <= m2); // skipped v <= half <= m2: exact
            if (__all_sync(0xffffffffu, done)) break;
            const int e = off[j + 1];
            for (int i = off[j] + chunk; i < e; i += 4) {
                float2 mh = pr[i];                    // warp-uniform -> broadcast
                float v = mh.y - fabsf(tv - mh.x);    // 2 FADD + below 3 FMNMX
                m2 = fmaxf(m2, fminf(m1, v));
                m1 = fmaxf(m1, v);
            }
        }
        s_part[dim][chunk][t] = make_float2(m1, m2);
    }
    __syncthreads();

    // ---- Merge the 4 chunks per (dim, t), write outputs
    if (tid < 256) {
        const int dim = tid >> 7;             // warp-uniform
        const int t   = tid & 127;
        float m1 = 0.0f;
        if (t < TPTS) {
            float2 a = s_part[dim][0][t];
            m1 = a.x; float m2 = a.y;
            #pragma unroll
            for (int c = 1; c < 4; c++) {
                float2 o = s_part[dim][c][t];
                float lo = fminf(m1, o.x);
                m1 = fmaxf(m1, o.x);
                m2 = fmaxf(fmaxf(lo, m2), o.y);
            }
            *(float2*)&land[((size_t)(b * 2 + dim) * TPTS + t) * 2] =
                make_float2(m1, m2);
        }
        unsigned wm = __reduce_max_sync(0xffffffffu, __float_as_uint(m1));
        if (lane == 0) atomicMax(&s_max[dim], wm);  // m1 >= 0: bit order OK
    }
    __syncthreads();

    if (tid < 2) {
        bool nz = (s_cnt[tid] > 0) && (__uint_as_float(s_max[tid]) > 0.0f);
        trange[b * 4 + 2 * tid + 0] = nz ? s_tmin[tid] : 0.0f;
        trange[b * 4 + 2 * tid + 1] = nz ? s_tmax[tid] : 0.0f;
    }
}

extern "C" void kernel_launch(void* const* d_in, const int* in_sizes, int n_in,
                              void* d_out, int out_size) {
    const float* inputs    = (const float*)d_in[0];
    const int*   dim_idx   = (const int*)  d_in[1];
    const int*   birth_loc = (const int*)  d_in[2];
    const int*   death_loc = (const int*)  d_in[3];

    float* land   = (float*)d_out;                        // B*2*T*2 = 102400
    float* trange = land + (size_t)BATCH * 2 * TPTS * 2;  // B*4     = 1024

    pl_kernel<<<BATCH, 1024>>>(inputs, dim_idx, birth_loc, death_loc, land, trange);
}

// round 6
// speedup vs baseline: 1.3633x; 1.3633x over previous
#include <cuda_runtime.h>
#include <cuda_bf16.h>

#define BATCH 256
#define PPAIR 1024
#define TPTS  100
#define NGRID 65536
#define NB    (TPTS + 1)   // mid-buckets 0..100
#define NBINS (2 * NB)     // flattened (dim, bucket)
#define SENT  (-1e30f)

__device__ __forceinline__ void top2_upd(float v, float& a1, float& a2) {
    a2 = fmaxf(a2, fminf(a1, v));
    a1 = fmaxf(a1, v);
}

__global__ __launch_bounds__(1024, 2)
void pl_kernel(const float* __restrict__ inputs,
               const int*   __restrict__ dim_idx,
               const int*   __restrict__ birth_loc,
               const int*   __restrict__ death_loc,
               float* __restrict__ land,    // [B, 2, T, 2]
               float* __restrict__ trange)  // [B, 4]
{
    __shared__ float  s_b[PPAIR], s_d[PPAIR];
    __shared__ unsigned char s_dm[PPAIR];
    __shared__ __align__(16) float2 s_pr[PPAIR];   // scattered (d, -b) by (dim,bucket)
    __shared__ int    s_hist[NBINS];               // histogram, then scatter cursor
    __shared__ int    s_off[NBINS + 1];            // bin start offsets
    __shared__ float2 s_scan[4][2][128];           // [dim*2+side][pingpong][j] top2
    __shared__ int    s_wsum[8];
    __shared__ int    s_cnt[2];
    __shared__ float  s_tmin[2], s_tmax[2];
    __shared__ unsigned s_max[2];

    const int b    = blockIdx.x;
    const int tid  = threadIdx.x;
    const int lane = tid & 31;

    if (tid < NBINS) s_hist[tid] = 0;
    if (tid < 2) { s_cnt[tid] = 0; s_max[tid] = 0u; }

    const float* __restrict__ row = inputs + (size_t)b * NGRID;

    // ---- Phase A: gather one pair per thread
    const int   dm = dim_idx  [b * PPAIR + tid];
    const float vb = __ldg(row + birth_loc[b * PPAIR + tid]);
    const float vd = __ldg(row + death_loc[b * PPAIR + tid]);
    s_dm[tid] = (unsigned char)dm; s_b[tid] = vb; s_d[tid] = vd;
    {
        unsigned mk1 = __ballot_sync(0xffffffffu, dm == 1);
        if (lane == 0) {
            atomicAdd(&s_cnt[1], __popc(mk1));
            atomicAdd(&s_cnt[0], 32 - __popc(mk1));
        }
    }
    __syncthreads();

    // ---- Phase B: t-range from FIRST 2 valid pairs in original order
    if (tid < 2) {
        const int dim = tid;
        float tmin = 1e30f, tmax = -1e30f;
        int found = 0;
        for (int p = 0; p < PPAIR && found < 2; p++) {
            if (s_dm[p] == dim) {
                tmin = fminf(tmin, s_b[p]);
                tmax = fmaxf(tmax, s_d[p]);
                found++;
            }
        }
        if (s_cnt[dim] == 0) { tmin = 0.0f; tmax = 0.0f; }
        s_tmin[dim] = tmin; s_tmax[dim] = tmax;
    }
    __syncthreads();

    // ---- Phase C: bucket index c = smallest j with tv_j >= mid; histogram
    int bin;
    {
        const float tmn  = s_tmin[dm], tmx = s_tmax[dm];
        const float mid  = 0.5f * (vb + vd);
        const float num  = mid - tmn;
        const float step = (tmx - tmn) * (1.0f / (float)(TPTS - 1));
        int c;
        if (num <= 0.0f)       c = 0;
        else if (step <= 0.0f) c = NB - 1;   // degenerate range: mid > tmn -> B side
        else                   c = min(NB - 1, (int)ceilf(num / step));
        bin = dm * NB + c;
        atomicAdd(&s_hist[bin], 1);
    }
    __syncthreads();

    // ---- Phase D: exclusive prefix over NBINS (warp scan + warp-sum scan)
    if (tid < 256) {
        int v = (tid < NBINS) ? s_hist[tid] : 0;
        int iv = v;
        #pragma unroll
        for (int o = 1; o < 32; o <<= 1) {
            int n = __shfl_up_sync(0xffffffffu, iv, o);
            if (lane >= o) iv += n;
        }
        if (lane == 31) s_wsum[tid >> 5] = iv;
        __syncwarp();
        // (warp sums combined after block sync below)
        s_off[tid] = iv - v;  // temporarily warp-local exclusive
    }
    __syncthreads();
    if (tid < 256) {
        int base = 0;
        for (int q = 0; q < (tid >> 5); q++) base += s_wsum[q];
        int excl = s_off[tid] + base;
        if (tid <= NBINS) s_off[tid] = excl;   // s_off[NBINS] = 1024
        if (tid < NBINS)  s_hist[tid] = excl;  // scatter cursor
    }
    __syncthreads();

    // ---- Phase E: scatter (d, -b) into bucket-contiguous order
    {
        int pos = atomicAdd(&s_hist[bin], 1);
        s_pr[pos] = make_float2(vd, -vb);
    }
    __syncthreads();

    // ---- Phase F: per-bin top2 of d and of -b; pad buckets 101..127 w/ sentinel
    if (tid < 512) {
        const int arr = tid >> 7, j = tid & 127;
        if (j > NB - 1)
            s_scan[arr][0][j] = make_float2(SENT, SENT);
    }
    if (tid < NBINS) {
        const int dim = (tid >= NB), c = tid - dim * NB;
        const int st = s_off[tid], en = s_off[tid + 1];
        float d1 = SENT, d2 = SENT, n1 = SENT, n2 = SENT;
        for (int i = st; i < en; i++) {
            float2 e = s_pr[i];
            top2_upd(e.x, d1, d2);
            top2_upd(e.y, n1, n2);
        }
        s_scan[dim * 2 + 0][0][c] = make_float2(d1, d2);  // A: death tops
        s_scan[dim * 2 + 1][0][c] = make_float2(n1, n2);  // B: (-birth) tops
    }
    __syncthreads();

    // ---- Phase G: Hillis-Steele top2 scan; side0 prefix (asc), side1 suffix (desc)
    {
        const int arr  = tid >> 7;          // 0..3 for tid<512
        const int j    = tid & 127;
        const int side = arr & 1;
        int p = 0;
        #pragma unroll
        for (int s = 1; s < 128; s <<= 1) {
            float2 res;
            if (tid < 512) {
                res = s_scan[arr][p][j];
                const int pj = side ? j + s : j - s;
                if (pj >= 0 && pj < 128) {
                    float2 o = s_scan[arr][p][pj];
                    float lo = fminf(res.x, o.x);
                    res.x = fmaxf(res.x, o.x);
                    res.y = fmaxf(lo, fmaxf(res.y, o.y));
                }
            }
            __syncthreads();
            if (tid < 512) s_scan[arr][p ^ 1][j] = res;
            __syncthreads();
            p ^= 1;
        }
    }
    const int FIN = 1;  // 7 steps -> final buffer 1

    // ---- Phase H: finalize per (dim, t)
    if (tid < 256) {
        const int dim = tid >> 7;
        const int t   = tid & 127;
        float m1 = 0.0f;
        if (t < TPTS) {
            const float tmn = s_tmin[dim], tmx = s_tmax[dim];
            const float tv  = tmn + (tmx - tmn) * ((float)t * (1.0f / (float)(TPTS - 1)));
            float2 A = s_scan[dim * 2 + 0][FIN][t];      // buckets 0..t  (mid <= tv)
            float2 Bs = s_scan[dim * 2 + 1][FIN][t + 1]; // buckets t+1.. (mid  > tv)
            float vA1 = A.x - tv,  vA2 = A.y - tv;       // d - tv
            float vB1 = Bs.x + tv, vB2 = Bs.y + tv;      // tv - b
            m1 = fmaxf(0.0f, fmaxf(vA1, vB1));
            float s2 = fmaxf(fminf(vA1, vB1), (vA1 >= vB1) ? vA2 : vB2);
            float m2 = fmaxf(0.0f, s2);
            *(float2*)&land[((size_t)(b * 2 + dim) * TPTS + t) * 2] =
                make_float2(m1, m2);
        }
        unsigned wm = __reduce_max_sync(0xffffffffu, __float_as_uint(m1));
        if (lane == 0) atomicMax(&s_max[dim], wm);  // m1 >= 0: bit order OK
    }
    __syncthreads();

    if (tid < 2) {
        bool nz = (s_cnt[tid] > 0) && (__uint_as_float(s_max[tid]) > 0.0f);
        trange[b * 4 + 2 * tid + 0] = nz ? s_tmin[tid] : 0.0f;
        trange[b * 4 + 2 * tid + 1] = nz ? s_tmax[tid] : 0.0f;
    }
}

extern "C" void kernel_launch(void* const* d_in, const int* in_sizes, int n_in,
                              void* d_out, int out_size) {
    const float* inputs    = (const float*)d_in[0];
    const int*   dim_idx   = (const int*)  d_in[1];
    const int*   birth_loc = (const int*)  d_in[2];
    const int*   death_loc = (const int*)  d_in[3];

    float* land   = (float*)d_out;                        // B*2*T*2 = 102400
    float* trange = land + (size_t)BATCH * 2 * TPTS * 2;  // B*4     = 1024

    pl_kernel<<<BATCH, 1024>>>(inputs, dim_idx, birth_loc, death_loc, land, trange);
}